// round 1
// baseline (speedup 1.0000x reference)
#include <cuda_runtime.h>

#define Hh 256
#define Ww 256
#define CIN 32
#define OCH 32
#define NB 4
#define NI 10
#define KOUT 8

// ---------------- device scratch (no allocations allowed) ----------------
__device__ float g_hxp[(size_t)NB * Hh * Ww * OCH];  // u = inv*hx + off, layout [b][y][x][c]
__device__ float g_gtab[NI * 9 * OCH];               // g[n][cls][c] = inv[c]*hk9
__device__ float g_P[NI * 9];                        // P[n][cls] = sum_c 0.6 v[c] g[n][cls][c]
__device__ float g_w6[OCH], g_w4[OCH];
__device__ float g_invc[OCH], g_offc[OCH];
__device__ int   g_active[NB * NI];
__device__ float g_b0;

// ---------------- f32x2 helpers ----------------
__device__ __forceinline__ unsigned long long pack2(float lo, float hi) {
    unsigned long long r;
    asm("mov.b64 %0,{%1,%2};" : "=l"(r) : "f"(lo), "f"(hi));
    return r;
}
__device__ __forceinline__ void fma2(unsigned long long& d, unsigned long long a, unsigned long long b) {
    asm("fma.rn.f32x2 %0,%1,%2,%3;" : "=l"(d) : "l"(a), "l"(b), "l"(d));
}
__device__ __forceinline__ float2 unpack2(unsigned long long v) {
    float2 f;
    asm("mov.b64 {%0,%1},%2;" : "=f"(f.x), "=f"(f.y) : "l"(v));
    return f;
}

// ---------------- prep: tiny tables, 1 block ----------------
__global__ void prep_kernel(const float* __restrict__ emb,    // [10,64]
                            const float* __restrict__ klin,   // [8,64]
                            const float* __restrict__ c1w,    // [32,40,3,3]
                            const float* __restrict__ gamma,
                            const float* __restrict__ beta,
                            const float* __restrict__ mean,
                            const float* __restrict__ var,
                            const float* __restrict__ c2w,    // [32]
                            const float* __restrict__ c2b) {
    __shared__ float sInst[NI * KOUT];       // 80
    __shared__ float sSk[OCH * KOUT * 9];    // 2304
    __shared__ float sInv[OCH];
    __shared__ float sV[OCH];
    const int t = threadIdx.x;

    if (t < NI * KOUT) {
        int n = t / KOUT, k = t % KOUT;
        float s = 0.f;
        for (int i = 0; i < 64; i++) s += emb[n * 64 + i] * klin[k * 64 + i];
        sInst[t] = s;
    }
    if (t < OCH) {
        float iv = gamma[t] * rsqrtf(var[t] + 1e-5f);
        sInv[t] = iv;
        g_invc[t] = iv;
        g_offc[t] = beta[t] - mean[t] * iv;
        float v = c2w[t];
        sV[t] = v;
        g_w6[t] = 0.6f * v;
        g_w4[t] = 0.4f * v;
    }
    if (t < NB * NI) g_active[t] = 0;
    if (t == 0) g_b0 = c2b[0];

    // per-class kernel-tap sums of w_k
    for (int e = t; e < OCH * KOUT * 9; e += blockDim.x) {
        int c = e / 72, k = (e / 9) % 8, cls = e % 9;
        int ry = cls / 3, rx = cls % 3;
        int dy0 = (ry == 0) ? 1 : 0, dy1 = (ry == 2) ? 1 : 2;
        int dx0 = (rx == 0) ? 1 : 0, dx1 = (rx == 2) ? 1 : 2;
        float s = 0.f;
        for (int dy = dy0; dy <= dy1; dy++)
            for (int dx = dx0; dx <= dx1; dx++)
                s += c1w[(c * 40 + (CIN + k)) * 9 + dy * 3 + dx];
        sSk[e] = s;
    }
    __syncthreads();

    for (int e = t; e < NI * 9 * OCH; e += blockDim.x) {
        int n = e / (9 * OCH), cls = (e / OCH) % 9, c = e % OCH;
        float s = 0.f;
        for (int k = 0; k < KOUT; k++) s += sInst[n * KOUT + k] * sSk[c * 72 + k * 9 + cls];
        g_gtab[(n * 9 + cls) * OCH + c] = sInv[c] * s;
    }
    __syncthreads();

    for (int e = t; e < NI * 9; e += blockDim.x) {
        int n = e / 9, cls = e % 9;
        float s = 0.f;
        for (int c = 0; c < OCH; c++) s += 0.6f * sV[c] * g_gtab[(n * 9 + cls) * OCH + c];
        g_P[e] = s;
    }
}

// ---------------- mask reduction: active[b,n] ----------------
__global__ void mask_kernel(const int* __restrict__ masks) {
    int m = blockIdx.x;  // 0..39
    const int4* p = (const int4*)(masks + (size_t)m * (Hh * Ww)) + blockIdx.y * 2048;
    int acc = 0;
    for (int i = threadIdx.x; i < 2048; i += blockDim.x) {
        int4 v = p[i];
        acc |= v.x | v.y | v.z | v.w;
    }
    if (__syncthreads_or(acc)) {
        if (threadIdx.x == 0) g_active[m] = 1;
    }
}

// ---------------- conv 3x3 (32->32) + BN affine, writes channel-last u ----------------
// block tile: 64 x-px, 4 rows, all 32 oc. thread: 4 px (x) * 8 oc, oc paired in f32x2.
__global__ __launch_bounds__(256, 2) void conv_kernel(const float* __restrict__ x,
                                                      const float* __restrict__ c1w) {
    extern __shared__ float sm[];
    float* sIn = sm;                  // [CIN][6][68]
    float* sW = sm + CIN * 6 * 68;    // [CIN][9][OCH], 32B aligned
    const int t = threadIdx.x;
    const int b = blockIdx.z;
    const int X0 = blockIdx.x * 64;
    const int Y0 = blockIdx.y * 4;

    // weights -> smem, layout [cin][tap][oc]
    for (int e = t; e < CIN * 9 * OCH; e += 256) {
        int oc = e & 31, tap = (e >> 5) % 9, cin = e / 288;
        sW[(cin * 9 + tap) * OCH + oc] = c1w[(oc * 40 + cin) * 9 + tap];
    }
    // input tile (with halo, zero-padded) -> smem
    const float* xb = x + (size_t)b * CIN * Hh * Ww;
    for (int e = t; e < CIN * 6 * 66; e += 256) {
        int col = e % 66, r = (e / 66) % 6, cin = e / 396;
        int gy = Y0 - 1 + r, gx = X0 - 1 + col;
        float v = 0.f;
        if ((unsigned)gy < Hh && (unsigned)gx < Ww) v = xb[(size_t)cin * Hh * Ww + gy * Ww + gx];
        sIn[(cin * 6 + r) * 68 + col] = v;
    }
    __syncthreads();

    const int xg = t & 15, ocg = (t >> 4) & 3, tyy = t >> 6;
    unsigned long long acc[4][4];
#pragma unroll
    for (int i = 0; i < 4; i++)
#pragma unroll
        for (int j = 0; j < 4; j++) acc[i][j] = 0ull;

#pragma unroll 1
    for (int cin = 0; cin < CIN; ++cin) {
        const float* base = sIn + (cin * 6 + tyy) * 68 + xg * 4;
        const float* wbase = sW + cin * 9 * OCH + ocg * 8;
#pragma unroll
        for (int ky = 0; ky < 3; ky++) {
            const float* row = base + ky * 68;
            unsigned long long s[6];
#pragma unroll
            for (int i = 0; i < 6; i++) {
                float f = row[i];
                s[i] = pack2(f, f);
            }
#pragma unroll
            for (int kx = 0; kx < 3; kx++) {
                const unsigned long long* wp =
                    (const unsigned long long*)(wbase + (ky * 3 + kx) * OCH);
                unsigned long long w0 = wp[0], w1 = wp[1], w2 = wp[2], w3 = wp[3];
#pragma unroll
                for (int px = 0; px < 4; px++) {
                    fma2(acc[0][px], w0, s[px + kx]);
                    fma2(acc[1][px], w1, s[px + kx]);
                    fma2(acc[2][px], w2, s[px + kx]);
                    fma2(acc[3][px], w3, s[px + kx]);
                }
            }
        }
    }

    // BN affine + channel-last store
    const int oc0 = ocg * 8;
    float inv[8], off[8];
#pragma unroll
    for (int j = 0; j < 8; j++) {
        inv[j] = g_invc[oc0 + j];
        off[j] = g_offc[oc0 + j];
    }
    const int y = Y0 + tyy;
#pragma unroll
    for (int px = 0; px < 4; px++) {
        float o[8];
#pragma unroll
        for (int op = 0; op < 4; op++) {
            float2 f = unpack2(acc[op][px]);
            o[op * 2] = f.x;
            o[op * 2 + 1] = f.y;
        }
#pragma unroll
        for (int j = 0; j < 8; j++) o[j] = fmaf(o[j], inv[j], off[j]);
        size_t pix = (size_t)b * Hh * Ww + (size_t)y * Ww + (X0 + xg * 4 + px);
        float4* dst = (float4*)(g_hxp + pix * OCH + oc0);
        dst[0] = make_float4(o[0], o[1], o[2], o[3]);
        dst[1] = make_float4(o[4], o[5], o[6], o[7]);
    }
}

// ---------------- epilogue: per-pixel, loop n, |t| trick ----------------
// block = one image row (256 px), grid = 4*256
__global__ __launch_bounds__(256) void epi_kernel(float* __restrict__ out) {
    __shared__ float sg[NI * 3 * OCH];  // [n][rx][c] for this row's ry
    __shared__ float sP[NI * 3];
    __shared__ float sw6[OCH], sw4[OCH];
    __shared__ int sact[NI];
    __shared__ float sb0;

    const int t = threadIdx.x;
    const int b = blockIdx.x >> 8;
    const int y = blockIdx.x & 255;
    const int ry = (y == 0) ? 0 : ((y == Hh - 1) ? 2 : 1);

    for (int e = t; e < NI * 3 * OCH; e += 256) {
        int n = e / (3 * OCH), rx = (e / OCH) % 3, c = e % OCH;
        sg[e] = g_gtab[(n * 9 + ry * 3 + rx) * OCH + c];
    }
    if (t < NI * 3) sP[t] = g_P[(t / 3) * 9 + ry * 3 + (t % 3)];
    if (t < OCH) {
        sw6[t] = g_w6[t];
        sw4[t] = g_w4[t];
    }
    if (t < NI) sact[t] = g_active[b * NI + t];
    if (t == 0) sb0 = g_b0;
    __syncthreads();

    const int xx = t;
    const int rx = (xx == 0) ? 0 : ((xx == Ww - 1) ? 2 : 1);
    const size_t pix = (size_t)y * Ww + xx;
    const float4* up = (const float4*)(g_hxp + ((size_t)b * Hh * Ww + pix) * OCH);

    float u[OCH];
#pragma unroll
    for (int q = 0; q < 8; q++) {
        float4 v = up[q];
        u[q * 4 + 0] = v.x;
        u[q * 4 + 1] = v.y;
        u[q * 4 + 2] = v.z;
        u[q * 4 + 3] = v.w;
    }
    float L = 0.f;
#pragma unroll
    for (int c = 0; c < OCH; c++) L = fmaf(sw6[c], u[c], L);

#pragma unroll 1
    for (int n = 0; n < NI; n++) {
        float r;
        if (sact[n]) {
            float a = L + sP[n * 3 + rx];
            const float* gn = sg + (n * 3 + rx) * OCH;
#pragma unroll
            for (int c = 0; c < OCH; c++) a = fmaf(sw4[c], fabsf(u[c] + gn[c]), a);
            r = a + sb0;
        } else {
            r = 0.f;
        }
        out[(size_t)(b * NI + n) * (Hh * Ww) + pix] = r;
    }
}

// ---------------- launch ----------------
extern "C" void kernel_launch(void* const* d_in, const int* in_sizes, int n_in,
                              void* d_out, int out_size) {
    const float* x = (const float*)d_in[0];
    const int* masks = (const int*)d_in[1];
    const float* emb = (const float*)d_in[2];
    const float* klin = (const float*)d_in[3];
    const float* c1w = (const float*)d_in[4];
    const float* gamma = (const float*)d_in[5];
    const float* beta = (const float*)d_in[6];
    const float* mean = (const float*)d_in[7];
    const float* var = (const float*)d_in[8];
    const float* c2w = (const float*)d_in[9];
    const float* c2b = (const float*)d_in[10];
    float* out = (float*)d_out;

    prep_kernel<<<1, 256>>>(emb, klin, c1w, gamma, beta, mean, var, c2w, c2b);
    mask_kernel<<<dim3(NB * NI, 8), 256>>>(masks);

    const size_t smem = (size_t)(CIN * 6 * 68 + CIN * 9 * OCH) * sizeof(float);
    cudaFuncSetAttribute(conv_kernel, cudaFuncAttributeMaxDynamicSharedMemorySize, (int)smem);
    conv_kernel<<<dim3(Ww / 64, Hh / 4, NB), 256, smem>>>(x, c1w);

    epi_kernel<<<NB * Hh, 256>>>(out);
}

// round 3
// speedup vs baseline: 1.6928x; 1.6928x over previous
#include <cuda_runtime.h>
#include <cstdint>

#define Hh 256
#define Ww 256
#define CIN 32
#define OCH 32
#define NB 4
#define NI 10
#define KOUT 8

#define XT 64    // px per block (x)
#define YT 8     // rows per block (one per warp)

// ---- smem byte offsets ----
#define SIN_OFF 0          // tf32 u32 [32][10][68]  = 87040 B
#define BF_OFF  87040      // B frags [9][4][4][32][2] u32 = 36864 B
#define GT_OFF  123904     // 10*9*32 f32
#define P_OFF   135424     // 90 f32
#define W6_OFF  135784
#define W4_OFF  135912
#define INV_OFF 136040
#define OFC_OFF 136168
#define ACT_OFF 136296     // 10 int
#define B0_OFF  136336
#define SMEM_TOTAL 136448

// ---- device globals ----
__device__ float g_gtab[NI * 9 * OCH];
__device__ float g_P[NI * 9];
__device__ float g_w6[OCH], g_w4[OCH];
__device__ float g_invc[OCH], g_offc[OCH];
__device__ int   g_active[NB * NI];
__device__ float g_b0;

__device__ __forceinline__ uint32_t f2tf32(float f) {
    uint32_t r;
    asm("cvt.rna.tf32.f32 %0, %1;" : "=r"(r) : "f"(f));
    return r;
}

__device__ __forceinline__ void mma_tf32(float* d, uint32_t a0, uint32_t a1,
                                         uint32_t a2, uint32_t a3,
                                         uint32_t b0, uint32_t b1) {
    asm volatile(
        "mma.sync.aligned.m16n8k8.row.col.f32.tf32.tf32.f32 "
        "{%0,%1,%2,%3},{%4,%5,%6,%7},{%8,%9},{%0,%1,%2,%3};"
        : "+f"(d[0]), "+f"(d[1]), "+f"(d[2]), "+f"(d[3])
        : "r"(a0), "r"(a1), "r"(a2), "r"(a3), "r"(b0), "r"(b1));
}

// ---------------- prep: tiny tables, 1 block ----------------
__global__ void prep_kernel(const float* __restrict__ emb, const float* __restrict__ klin,
                            const float* __restrict__ c1w, const float* __restrict__ gamma,
                            const float* __restrict__ beta, const float* __restrict__ mean,
                            const float* __restrict__ var, const float* __restrict__ c2w,
                            const float* __restrict__ c2b) {
    __shared__ float sInst[NI * KOUT];
    __shared__ float sSk[OCH * KOUT * 9];
    __shared__ float sInv[OCH];
    __shared__ float sV[OCH];
    const int t = threadIdx.x;

    if (t < NI * KOUT) {
        int n = t / KOUT, k = t % KOUT;
        float s = 0.f;
        for (int i = 0; i < 64; i++) s += emb[n * 64 + i] * klin[k * 64 + i];
        sInst[t] = s;
    }
    if (t < OCH) {
        float iv = gamma[t] * rsqrtf(var[t] + 1e-5f);
        sInv[t] = iv;
        g_invc[t] = iv;
        g_offc[t] = beta[t] - mean[t] * iv;
        float v = c2w[t];
        sV[t] = v;
        g_w6[t] = 0.6f * v;
        g_w4[t] = 0.4f * v;
    }
    if (t < NB * NI) g_active[t] = 0;
    if (t == 0) g_b0 = c2b[0];

    for (int e = t; e < OCH * KOUT * 9; e += blockDim.x) {
        int c = e / 72, k = (e / 9) % 8, cls = e % 9;
        int ry = cls / 3, rx = cls % 3;
        int dy0 = (ry == 0) ? 1 : 0, dy1 = (ry == 2) ? 1 : 2;
        int dx0 = (rx == 0) ? 1 : 0, dx1 = (rx == 2) ? 1 : 2;
        float s = 0.f;
        for (int dy = dy0; dy <= dy1; dy++)
            for (int dx = dx0; dx <= dx1; dx++)
                s += c1w[(c * 40 + (CIN + k)) * 9 + dy * 3 + dx];
        sSk[e] = s;
    }
    __syncthreads();

    for (int e = t; e < NI * 9 * OCH; e += blockDim.x) {
        int n = e / (9 * OCH), cls = (e / OCH) % 9, c = e % OCH;
        float s = 0.f;
        for (int k = 0; k < KOUT; k++) s += sInst[n * KOUT + k] * sSk[c * 72 + k * 9 + cls];
        g_gtab[(n * 9 + cls) * OCH + c] = sInv[c] * s;
    }
    __syncthreads();

    for (int e = t; e < NI * 9; e += blockDim.x) {
        int n = e / 9, cls = e % 9;
        float s = 0.f;
        for (int c = 0; c < OCH; c++) s += 0.6f * sV[c] * g_gtab[(n * 9 + cls) * OCH + c];
        g_P[e] = s;
    }
}

// ---------------- mask reduction ----------------
__global__ void mask_kernel(const int* __restrict__ masks) {
    int m = blockIdx.x;
    const int4* p = (const int4*)(masks + (size_t)m * (Hh * Ww)) + blockIdx.y * 2048;
    int acc = 0;
    for (int i = threadIdx.x; i < 2048; i += blockDim.x) {
        int4 v = p[i];
        acc |= v.x | v.y | v.z | v.w;
    }
    if (__syncthreads_or(acc)) {
        if (threadIdx.x == 0) g_active[m] = 1;
    }
}

// ---------------- fused conv (mma.sync tf32) + BN + leaky + head ----------------
__global__ __launch_bounds__(256, 1)
void conv_mma_kernel(const float* __restrict__ x, const float* __restrict__ c1w,
                     float* __restrict__ out) {
    extern __shared__ char smem[];
    uint32_t* sInU = (uint32_t*)(smem + SIN_OFF);
    const uint2* sBf2 = (const uint2*)(smem + BF_OFF);
    float* sGT = (float*)(smem + GT_OFF);
    float* sP = (float*)(smem + P_OFF);
    float* sW6 = (float*)(smem + W6_OFF);
    float* sW4 = (float*)(smem + W4_OFF);
    float* sInv = (float*)(smem + INV_OFF);
    float* sOfc = (float*)(smem + OFC_OFF);
    int* sAct = (int*)(smem + ACT_OFF);
    float* sB0 = (float*)(smem + B0_OFF);

    const int tid = threadIdx.x;
    const int w = tid >> 5, lid = tid & 31;
    const int grp = lid >> 2, tg = lid & 3;
    const int b = blockIdx.z;
    const int X0 = blockIdx.x * XT;
    const int Y0 = blockIdx.y * YT;

    // ---- B fragments: sBf[((tap*4+ks)*4+nt)*64 + lane*2 + r] ----
    {
        uint32_t* sBfU = (uint32_t*)(smem + BF_OFF);
        for (int e = tid; e < 9 * 4 * 4 * 64; e += 256) {
            int r = e & 1, lane = (e >> 1) & 31, nt = (e >> 6) & 3;
            int ks = (e >> 8) & 3, tap = e >> 10;
            int oc = nt * 8 + (lane >> 2);
            int cin = ks * 8 + (lane & 3) + r * 4;
            sBfU[e] = f2tf32(c1w[(oc * 40 + cin) * 9 + tap]);
        }
    }
    // ---- input tile -> tf32 smem [cin][10][68] ----
    {
        const float* xb = x + (size_t)b * CIN * Hh * Ww;
        for (int e = tid; e < CIN * 10 * 66; e += 256) {
            int col = e % 66, r = (e / 66) % 10, cin = e / 660;
            int gy = Y0 - 1 + r, gx = X0 - 1 + col;
            float v = 0.f;
            if ((unsigned)gy < Hh && (unsigned)gx < Ww)
                v = xb[(size_t)cin * (Hh * Ww) + gy * Ww + gx];
            sInU[cin * 680 + r * 68 + col] = f2tf32(v);
        }
    }
    // ---- tables ----
    for (int e = tid; e < NI * 9 * OCH; e += 256) sGT[e] = g_gtab[e];
    if (tid < NI * 9) sP[tid] = g_P[tid];
    if (tid < OCH) {
        sW6[tid] = g_w6[tid];
        sW4[tid] = g_w4[tid];
        sInv[tid] = g_invc[tid];
        sOfc[tid] = g_offc[tid];
    }
    if (tid < NI) sAct[tid] = g_active[b * NI + tid];
    if (tid == 0) sB0[0] = g_b0;
    __syncthreads();

    // ---- MMA mainloop: warp w computes row y=Y0+w, 64 px x 32 oc ----
    float d[4][4][4];
#pragma unroll
    for (int mt = 0; mt < 4; mt++)
#pragma unroll
        for (int nt = 0; nt < 4; nt++)
#pragma unroll
            for (int r = 0; r < 4; r++) d[mt][nt][r] = 0.f;

    const int abase = tg * 680 + w * 68 + grp;  // cin=tg, row=w, col=grp

#pragma unroll 1
    for (int tap = 0; tap < 9; tap++) {
        const int dy = tap / 3, dx = tap % 3;
        const int tb = abase + dy * 68 + dx;
#pragma unroll
        for (int ks = 0; ks < 4; ks++) {
            const int ab = tb + ks * 5440;  // +8 cin = 8*680
            uint2 bf0 = sBf2[((tap * 4 + ks) * 4 + 0) * 32 + lid];
            uint2 bf1 = sBf2[((tap * 4 + ks) * 4 + 1) * 32 + lid];
            uint2 bf2 = sBf2[((tap * 4 + ks) * 4 + 2) * 32 + lid];
            uint2 bf3 = sBf2[((tap * 4 + ks) * 4 + 3) * 32 + lid];
#pragma unroll
            for (int mt = 0; mt < 4; mt++) {
                const int am = ab + mt * 16;
                uint32_t a0 = sInU[am];
                uint32_t a1 = sInU[am + 8];
                uint32_t a2 = sInU[am + 2720];
                uint32_t a3 = sInU[am + 2728];
                mma_tf32(d[mt][0], a0, a1, a2, a3, bf0.x, bf0.y);
                mma_tf32(d[mt][1], a0, a1, a2, a3, bf1.x, bf1.y);
                mma_tf32(d[mt][2], a0, a1, a2, a3, bf2.x, bf2.y);
                mma_tf32(d[mt][3], a0, a1, a2, a3, bf3.x, bf3.y);
            }
        }
    }

    __syncthreads();  // done reading sIn; reuse as D staging

    // ---- stage D to smem [px][pitch 37] per warp ----
    float* sD = (float*)smem + w * 2368;
#pragma unroll
    for (int mt = 0; mt < 4; mt++) {
        const int px0 = mt * 16 + grp;
#pragma unroll
        for (int nt = 0; nt < 4; nt++) {
            const int oc0 = nt * 8 + tg * 2;
            sD[px0 * 37 + oc0] = d[mt][nt][0];
            sD[px0 * 37 + oc0 + 1] = d[mt][nt][1];
            sD[(px0 + 8) * 37 + oc0] = d[mt][nt][2];
            sD[(px0 + 8) * 37 + oc0 + 1] = d[mt][nt][3];
        }
    }
    __syncwarp();

    // ---- fused epilogue: BN affine + leaky algebra + 10-instance head ----
    const int gy = Y0 + w;
    const int ry = (gy == 0) ? 0 : ((gy == Hh - 1) ? 2 : 1);
    const float bias0 = sB0[0];

#pragma unroll
    for (int rep = 0; rep < 2; rep++) {
        const int p = lid + rep * 32;
        const int gx = X0 + p;
        const float* sDp = sD + p * 37;

        float u[OCH];
        float L = 0.f;
#pragma unroll
        for (int c = 0; c < OCH; c++) {
            u[c] = fmaf(sDp[c], sInv[c], sOfc[c]);
            L = fmaf(sW6[c], u[c], L);
        }
        const int rx = (gx == 0) ? 0 : ((gx == Ww - 1) ? 2 : 1);
        const int cls = ry * 3 + rx;
        const float base = L + bias0;
        float* op = out + (size_t)b * NI * (Hh * Ww) + (size_t)gy * Ww + gx;
#pragma unroll 1
        for (int n = 0; n < NI; n++) {
            float r = 0.f;
            if (sAct[n]) {
                float a = base + sP[n * 9 + cls];
                const float* gn = sGT + (n * 9 + cls) * OCH;
#pragma unroll
                for (int c = 0; c < OCH; c++) a = fmaf(sW4[c], fabsf(u[c] + gn[c]), a);
                r = a;
            }
            op[(size_t)n * (Hh * Ww)] = r;
        }
    }
}

// ---------------- launch ----------------
extern "C" void kernel_launch(void* const* d_in, const int* in_sizes, int n_in,
                              void* d_out, int out_size) {
    const float* x = (const float*)d_in[0];
    const int* masks = (const int*)d_in[1];
    const float* emb = (const float*)d_in[2];
    const float* klin = (const float*)d_in[3];
    const float* c1w = (const float*)d_in[4];
    const float* gamma = (const float*)d_in[5];
    const float* beta = (const float*)d_in[6];
    const float* mean = (const float*)d_in[7];
    const float* var = (const float*)d_in[8];
    const float* c2w = (const float*)d_in[9];
    const float* c2b = (const float*)d_in[10];
    float* out = (float*)d_out;

    prep_kernel<<<1, 256>>>(emb, klin, c1w, gamma, beta, mean, var, c2w, c2b);
    mask_kernel<<<dim3(NB * NI, 8), 256>>>(masks);

    cudaFuncSetAttribute(conv_mma_kernel, cudaFuncAttributeMaxDynamicSharedMemorySize,
                         SMEM_TOTAL);
    conv_mma_kernel<<<dim3(Ww / XT, Hh / YT, NB), 256, SMEM_TOTAL>>>(x, c1w, out);
}